// round 4
// baseline (speedup 1.0000x reference)
#include <cuda_runtime.h>
#include <math.h>
#include <limits.h>

#define HDIM    128
#define SDIM    32
#define KTOP    8
#define EPB     128      // embeddings per block
#define THREADS 256

// Scratch (__device__ globals; no allocation allowed)
__device__ float g_cand_v[1024 * KTOP];
__device__ int   g_cand_i[1024 * KTOP];
__device__ unsigned int g_ticket;        // monotonically increasing across replays

__device__ __forceinline__ bool better(float va, int ia, float vb, int ib) {
    // jax.lax.top_k ordering: higher value first, ties -> lower index
    return (va > vb) || (va == vb && ia < ib);
}

__device__ __forceinline__ void insert_topk(float* lv, int* li, float v, int c) {
    if (better(v, c, lv[KTOP - 1], li[KTOP - 1])) {
        int j = KTOP - 1;
#pragma unroll
        for (; j > 0; --j) {
            if (better(v, c, lv[j - 1], li[j - 1])) {
                lv[j] = lv[j - 1];
                li[j] = li[j - 1];
            } else break;
        }
        lv[j] = v;
        li[j] = c;
    }
}

__global__ void fused_kernel(const float* __restrict__ q,
                             const float* __restrict__ emb,
                             const float* __restrict__ episodes,
                             float* __restrict__ out,
                             int C) {
    __shared__ float sq[HDIM];
    __shared__ float s_rqn;
    __shared__ float s_sims[EPB];
    __shared__ float sv[THREADS * KTOP];
    __shared__ int   si[THREADS * KTOP];
    __shared__ int   s_amlast;

    const int t = threadIdx.x;

    // ---- query row 0 into smem + 1/||q|| ----
    if (t < HDIM) sq[t] = q[t];
    __syncthreads();
    if (t < 32) {
        const float4 a = reinterpret_cast<const float4*>(sq)[t];
        float s = a.x * a.x + a.y * a.y + a.z * a.z + a.w * a.w;
#pragma unroll
        for (int o = 16; o; o >>= 1) s += __shfl_xor_sync(0xffffffffu, s, o);
        if (t == 0) s_rqn = 1.0f / fmaxf(sqrtf(s), 1e-8f);
    }
    __syncthreads();
    const float rqn = s_rqn;

    // ---- cosine sims: 2 lanes per embedding, 128 embeddings per block ----
    const int gid  = blockIdx.x * THREADS + t;
    const int c    = gid >> 1;
    const int half = gid & 1;
    const int cs   = (c < C) ? c : (C - 1);

    const float4* __restrict__ row = reinterpret_cast<const float4*>(emb + (size_t)cs * HDIM);
    const float4* __restrict__ qv  = reinterpret_cast<const float4*>(sq);

    float d0 = 0.f, d1 = 0.f, e0 = 0.f, e1 = 0.f;
#pragma unroll 4
    for (int i = 0; i < 16; ++i) {
        const int idx = half + 2 * i;
        const float4 ev = row[idx];
        const float4 qq = qv[idx];
        d0 += ev.x * qq.x + ev.y * qq.y;
        d1 += ev.z * qq.z + ev.w * qq.w;
        e0 += ev.x * ev.x + ev.y * ev.y;
        e1 += ev.z * ev.z + ev.w * ev.w;
    }
    float dot = d0 + d1;
    float esq = e0 + e1;
    dot += __shfl_xor_sync(0xffffffffu, dot, 1);
    esq += __shfl_xor_sync(0xffffffffu, esq, 1);

    if (half == 0)
        s_sims[t >> 1] = (c < C) ? dot * rqn / fmaxf(sqrtf(esq), 1e-8f) : -INFINITY;
    __syncthreads();

    // ---- block top-8: 16 threads x 8 sims, then 4-level merge tree ----
    if (t < 16) {
        float lv[KTOP]; int li[KTOP];
#pragma unroll
        for (int j = 0; j < KTOP; ++j) { lv[j] = -INFINITY; li[j] = INT_MAX; }
        const int base_g = blockIdx.x * EPB;
#pragma unroll
        for (int j = 0; j < 8; ++j)
            insert_topk(lv, li, s_sims[t * 8 + j], base_g + t * 8 + j);
#pragma unroll
        for (int j = 0; j < KTOP; ++j) { sv[t * KTOP + j] = lv[j]; si[t * KTOP + j] = li[j]; }
    }
    __syncthreads();
    for (int s = 8; s > 0; s >>= 1) {
        if (t < s) {
            float mv[KTOP]; int mi[KTOP];
            int a = 0, b = 0;
#pragma unroll
            for (int j = 0; j < KTOP; ++j) {
                const float va = sv[t * KTOP + a];       const int ia = si[t * KTOP + a];
                const float vb = sv[(t + s) * KTOP + b]; const int ib = si[(t + s) * KTOP + b];
                if (better(va, ia, vb, ib)) { mv[j] = va; mi[j] = ia; ++a; }
                else                        { mv[j] = vb; mi[j] = ib; ++b; }
            }
#pragma unroll
            for (int j = 0; j < KTOP; ++j) { sv[t * KTOP + j] = mv[j]; si[t * KTOP + j] = mi[j]; }
        }
        __syncthreads();
    }
    if (t < KTOP) {
        g_cand_v[blockIdx.x * KTOP + t] = sv[t];
        g_cand_i[blockIdx.x * KTOP + t] = si[t];
    }

    // ---- last-block election (no reset needed: modulo survives graph replays) ----
    __threadfence();
    __syncthreads();
    if (t == 0) {
        const unsigned int old = atomicAdd(&g_ticket, 1u);
        s_amlast = ((old % gridDim.x) == gridDim.x - 1);
    }
    __syncthreads();
    if (!s_amlast) return;
    __threadfence();   // acquire side

    // ---- final merge: nblocks*KTOP candidates -> global top-8 ----
    const int ncand = gridDim.x * KTOP;
    {
        float lv[KTOP]; int li[KTOP];
#pragma unroll
        for (int j = 0; j < KTOP; ++j) { lv[j] = -INFINITY; li[j] = INT_MAX; }
        for (int cc = t; cc < ncand; cc += THREADS)
            insert_topk(lv, li, __ldcg(&g_cand_v[cc]), __ldcg(&g_cand_i[cc]));
#pragma unroll
        for (int j = 0; j < KTOP; ++j) { sv[t * KTOP + j] = lv[j]; si[t * KTOP + j] = li[j]; }
    }
    __syncthreads();
    for (int s = 128; s > 0; s >>= 1) {
        if (t < s) {
            float mv[KTOP]; int mi[KTOP];
            int a = 0, b = 0;
#pragma unroll
            for (int j = 0; j < KTOP; ++j) {
                const float va = sv[t * KTOP + a];       const int ia = si[t * KTOP + a];
                const float vb = sv[(t + s) * KTOP + b]; const int ib = si[(t + s) * KTOP + b];
                if (better(va, ia, vb, ib)) { mv[j] = va; mi[j] = ia; ++a; }
                else                        { mv[j] = vb; mi[j] = ib; ++b; }
            }
#pragma unroll
            for (int j = 0; j < KTOP; ++j) { sv[t * KTOP + j] = mv[j]; si[t * KTOP + j] = mi[j]; }
        }
        __syncthreads();
    }
    // top-8 now in sv[0..7] / si[0..7]

    // ---- gather the 8 episodes [8,32,128] + write scores ----
    const int n4 = KTOP * SDIM * HDIM / 4;     // 8192 float4
    const float4* __restrict__ epi4 = reinterpret_cast<const float4*>(episodes);
    float4* __restrict__ out4 = reinterpret_cast<float4*>(out);
#pragma unroll 4
    for (int j = t; j < n4; j += THREADS) {
        const int e   = j >> 10;               // 1024 float4 per episode
        const int off = j & 1023;
        const int idx = si[e];
        out4[j] = epi4[(size_t)idx * (SDIM * HDIM / 4) + off];
    }
    if (t < KTOP)
        out[KTOP * SDIM * HDIM + t] = sv[t];   // top_scores[0]
}

extern "C" void kernel_launch(void* const* d_in, const int* in_sizes, int n_in,
                              void* d_out, int out_size) {
    const float* query    = (const float*)d_in[0];  // [B, 128]
    const float* episodes = (const float*)d_in[1];  // [C, 32, 128]
    const float* emb      = (const float*)d_in[2];  // [C, 128]
    (void)n_in; (void)out_size;

    const int C = in_sizes[2] / HDIM;               // 100000
    const int nblocks = (C + EPB - 1) / EPB;        // 782

    fused_kernel<<<nblocks, THREADS>>>(query, emb, episodes, (float*)d_out, C);
}

// round 5
// speedup vs baseline: 1.5122x; 1.5122x over previous
#include <cuda_runtime.h>
#include <math.h>
#include <limits.h>

#define HDIM 128
#define SDIM 32
#define KTOP 8
#define NB1  128      // stage-1 top-k blocks

// Scratch (__device__ globals; no allocation allowed)
__device__ float g_sims[100096];          // padded past C
__device__ float g_cand_v[NB1 * KTOP];
__device__ int   g_cand_i[NB1 * KTOP];

__device__ __forceinline__ bool better(float va, int ia, float vb, int ib) {
    // jax.lax.top_k ordering: higher value first, ties -> lower index
    return (va > vb) || (va == vb && ia < ib);
}

__device__ __forceinline__ void insert_topk(float* lv, int* li, float v, int c) {
    if (better(v, c, lv[KTOP - 1], li[KTOP - 1])) {
        int j = KTOP - 1;
#pragma unroll
        for (; j > 0; --j) {
            if (better(v, c, lv[j - 1], li[j - 1])) {
                lv[j] = lv[j - 1];
                li[j] = li[j - 1];
            } else break;
        }
        lv[j] = v;
        li[j] = c;
    }
}

// ---------------------------------------------------------------------------
// Kernel 1: cosine sims, 2 lanes per embedding, front-batched loads (MLP=16).
// Lane pair (2k,2k+1) reads 32B-contiguous interleaved halves of one row.
// All 16 float4 loads are issued into registers before any FMA consumes them.
// ---------------------------------------------------------------------------
__global__ void __launch_bounds__(256) sims_kernel(const float* __restrict__ q,
                                                   const float* __restrict__ emb,
                                                   int C) {
    __shared__ float sq[HDIM];
    __shared__ float s_rqn;
    const int t = threadIdx.x;

    if (t < HDIM) sq[t] = q[t];               // query row 0
    __syncthreads();
    if (t < 32) {
        const float4 a = reinterpret_cast<const float4*>(sq)[t];
        float s = a.x * a.x + a.y * a.y + a.z * a.z + a.w * a.w;
#pragma unroll
        for (int o = 16; o; o >>= 1) s += __shfl_xor_sync(0xffffffffu, s, o);
        if (t == 0) s_rqn = 1.0f / fmaxf(sqrtf(s), 1e-8f);
    }
    __syncthreads();
    const float rqn = s_rqn;

    const int gid  = blockIdx.x * blockDim.x + t;
    const int c    = gid >> 1;                // embedding index
    const int half = gid & 1;                 // which half of the row
    const int cs   = (c < C) ? c : (C - 1);   // clamp; guard only the store

    const float4* __restrict__ row = reinterpret_cast<const float4*>(emb + (size_t)cs * HDIM);
    const float4* __restrict__ qv  = reinterpret_cast<const float4*>(sq);

    // Front-batched loads: 16 independent LDG.128 in flight per thread.
    float4 ev[16];
#pragma unroll
    for (int i = 0; i < 16; ++i) ev[i] = row[half + 2 * i];

    float d0 = 0.f, d1 = 0.f, e0 = 0.f, e1 = 0.f;
#pragma unroll
    for (int i = 0; i < 16; ++i) {
        const float4 qq = qv[half + 2 * i];
        d0 += ev[i].x * qq.x + ev[i].y * qq.y;
        d1 += ev[i].z * qq.z + ev[i].w * qq.w;
        e0 += ev[i].x * ev[i].x + ev[i].y * ev[i].y;
        e1 += ev[i].z * ev[i].z + ev[i].w * ev[i].w;
    }
    float dot = d0 + d1;
    float esq = e0 + e1;
    dot += __shfl_xor_sync(0xffffffffu, dot, 1);
    esq += __shfl_xor_sync(0xffffffffu, esq, 1);

    if (half == 0 && c < C)
        g_sims[c] = dot * rqn / fmaxf(sqrtf(esq), 1e-8f);
}

// ---------------------------------------------------------------------------
// Kernel 2: stage-1 top-8. 128 blocks grid-stride over g_sims,
// per-thread sorted list, then smem merge tree.
// ---------------------------------------------------------------------------
__global__ void topk_stage1(int C) {
    __shared__ float sv[256 * KTOP];
    __shared__ int   si[256 * KTOP];
    const int t = threadIdx.x;

    float lv[KTOP]; int li[KTOP];
#pragma unroll
    for (int j = 0; j < KTOP; ++j) { lv[j] = -INFINITY; li[j] = INT_MAX; }

    for (int c = blockIdx.x * blockDim.x + t; c < C; c += gridDim.x * blockDim.x)
        insert_topk(lv, li, g_sims[c], c);

#pragma unroll
    for (int j = 0; j < KTOP; ++j) { sv[t * KTOP + j] = lv[j]; si[t * KTOP + j] = li[j]; }
    __syncthreads();

    for (int s = 128; s > 0; s >>= 1) {
        if (t < s) {
            float mv[KTOP]; int mi[KTOP];
            int a = 0, b = 0;
#pragma unroll
            for (int j = 0; j < KTOP; ++j) {
                const float va = sv[t * KTOP + a];       const int ia = si[t * KTOP + a];
                const float vb = sv[(t + s) * KTOP + b]; const int ib = si[(t + s) * KTOP + b];
                if (better(va, ia, vb, ib)) { mv[j] = va; mi[j] = ia; ++a; }
                else                        { mv[j] = vb; mi[j] = ib; ++b; }
            }
#pragma unroll
            for (int j = 0; j < KTOP; ++j) { sv[t * KTOP + j] = mv[j]; si[t * KTOP + j] = mi[j]; }
        }
        __syncthreads();
    }

    if (t < KTOP) {
        g_cand_v[blockIdx.x * KTOP + t] = sv[t];
        g_cand_i[blockIdx.x * KTOP + t] = si[t];
    }
}

// ---------------------------------------------------------------------------
// Kernel 3: final merge (1024 candidates -> top-8) + gather + scores.
// One block, 1024 threads. Threads 0..255 run the merge; everyone gathers.
// ---------------------------------------------------------------------------
__global__ void __launch_bounds__(1024) final_gather(const float* __restrict__ episodes,
                                                     float* __restrict__ out) {
    __shared__ float sv[256 * KTOP];
    __shared__ int   si[256 * KTOP];
    const int t = threadIdx.x;

    if (t < 256) {
        float lv[KTOP]; int li[KTOP];
#pragma unroll
        for (int j = 0; j < KTOP; ++j) { lv[j] = -INFINITY; li[j] = INT_MAX; }
        for (int c = t; c < NB1 * KTOP; c += 256)
            insert_topk(lv, li, g_cand_v[c], g_cand_i[c]);
#pragma unroll
        for (int j = 0; j < KTOP; ++j) { sv[t * KTOP + j] = lv[j]; si[t * KTOP + j] = li[j]; }
    }
    __syncthreads();

    for (int s = 128; s > 0; s >>= 1) {
        if (t < s) {
            float mv[KTOP]; int mi[KTOP];
            int a = 0, b = 0;
#pragma unroll
            for (int j = 0; j < KTOP; ++j) {
                const float va = sv[t * KTOP + a];       const int ia = si[t * KTOP + a];
                const float vb = sv[(t + s) * KTOP + b]; const int ib = si[(t + s) * KTOP + b];
                if (better(va, ia, vb, ib)) { mv[j] = va; mi[j] = ia; ++a; }
                else                        { mv[j] = vb; mi[j] = ib; ++b; }
            }
#pragma unroll
            for (int j = 0; j < KTOP; ++j) { sv[t * KTOP + j] = mv[j]; si[t * KTOP + j] = mi[j]; }
        }
        __syncthreads();
    }
    // global top-8 in sv[0..7] / si[0..7]

    // ---- gather 8 episodes [8,32,128]: 8192 float4, 8 per thread, independent
    const float4* __restrict__ epi4 = reinterpret_cast<const float4*>(episodes);
    float4* __restrict__ out4 = reinterpret_cast<float4*>(out);
#pragma unroll
    for (int r = 0; r < 8; ++r) {
        const int j   = r * 1024 + t;          // 0..8191
        const int e   = j >> 10;               // episode slot (1024 float4 each)
        const int off = j & 1023;
        const int idx = si[e];
        out4[j] = epi4[(size_t)idx * (SDIM * HDIM / 4) + off];
    }
    if (t < KTOP)
        out[KTOP * SDIM * HDIM + t] = sv[t];   // top_scores[0]
}

extern "C" void kernel_launch(void* const* d_in, const int* in_sizes, int n_in,
                              void* d_out, int out_size) {
    const float* query    = (const float*)d_in[0];  // [B, 128]
    const float* episodes = (const float*)d_in[1];  // [C, 32, 128]
    const float* emb      = (const float*)d_in[2];  // [C, 128]
    (void)n_in; (void)out_size;

    const int C = in_sizes[2] / HDIM;               // 100000

    const int blocksA = (2 * C + 255) / 256;        // 2 lanes per embedding
    sims_kernel<<<blocksA, 256>>>(query, emb, C);
    topk_stage1<<<NB1, 256>>>(C);
    final_gather<<<1, 1024>>>(episodes, (float*)d_out);
}

// round 6
// speedup vs baseline: 1.5262x; 1.0092x over previous
#include <cuda_runtime.h>
#include <math.h>
#include <limits.h>

#define HDIM 128
#define SDIM 32
#define KTOP 8
#define NB1  128      // stage-1 top-k blocks

// Scratch (__device__ globals; no allocation allowed)
__device__ float g_sims[100096];          // padded past C
__device__ float g_cand_v[NB1 * KTOP];
__device__ int   g_cand_i[NB1 * KTOP];

__device__ __forceinline__ bool better(float va, int ia, float vb, int ib) {
    // jax.lax.top_k ordering: higher value first, ties -> lower index
    return (va > vb) || (va == vb && ia < ib);
}

__device__ __forceinline__ void insert_topk(float* lv, int* li, float v, int c) {
    if (better(v, c, lv[KTOP - 1], li[KTOP - 1])) {
        int j = KTOP - 1;
#pragma unroll
        for (; j > 0; --j) {
            if (better(v, c, lv[j - 1], li[j - 1])) {
                lv[j] = lv[j - 1];
                li[j] = li[j - 1];
            } else break;
        }
        lv[j] = v;
        li[j] = c;
    }
}

// ---------------------------------------------------------------------------
// Kernel 1: cosine sims, 2 lanes per embedding.
// __launch_bounds__(256, 4) -> 64-reg budget so the two 8-wide load batches
// genuinely stay in flight (MLP ~8-16), instead of being rolled back to ~6
// by the register allocator (R5: regs=33, DRAM 46%).
// Wave 2's loads are issued BEFORE wave 1's FMAs consume anything.
// ---------------------------------------------------------------------------
__global__ void __launch_bounds__(256, 4)
sims_kernel(const float* __restrict__ q,
            const float* __restrict__ emb,
            int C) {
    __shared__ float sq[HDIM];
    __shared__ float s_rqn;
    const int t = threadIdx.x;

    if (t < HDIM) sq[t] = q[t];               // query row 0
    __syncthreads();
    if (t < 32) {
        const float4 a = reinterpret_cast<const float4*>(sq)[t];
        float s = a.x * a.x + a.y * a.y + a.z * a.z + a.w * a.w;
#pragma unroll
        for (int o = 16; o; o >>= 1) s += __shfl_xor_sync(0xffffffffu, s, o);
        if (t == 0) s_rqn = 1.0f / fmaxf(sqrtf(s), 1e-8f);
    }
    __syncthreads();
    const float rqn = s_rqn;

    const int gid  = blockIdx.x * blockDim.x + t;
    const int c    = gid >> 1;                // embedding index
    const int half = gid & 1;                 // which half of the row
    const int cs   = (c < C) ? c : (C - 1);   // clamp; guard only the store

    const float4* __restrict__ row = reinterpret_cast<const float4*>(emb + (size_t)cs * HDIM);
    const float4* __restrict__ qv  = reinterpret_cast<const float4*>(sq);

    // Batch 1: 8 LDG.128 in flight
    float4 ev0[8];
#pragma unroll
    for (int i = 0; i < 8; ++i) ev0[i] = row[half + 2 * i];
    // Batch 2: 8 more LDG.128 issued before any FMA consumes batch 1
    float4 ev1[8];
#pragma unroll
    for (int i = 0; i < 8; ++i) ev1[i] = row[half + 2 * (i + 8)];

    float d0 = 0.f, d1 = 0.f, e0 = 0.f, e1 = 0.f;
#pragma unroll
    for (int i = 0; i < 8; ++i) {
        const float4 qq = qv[half + 2 * i];
        d0 += ev0[i].x * qq.x + ev0[i].y * qq.y;
        d1 += ev0[i].z * qq.z + ev0[i].w * qq.w;
        e0 += ev0[i].x * ev0[i].x + ev0[i].y * ev0[i].y;
        e1 += ev0[i].z * ev0[i].z + ev0[i].w * ev0[i].w;
    }
#pragma unroll
    for (int i = 0; i < 8; ++i) {
        const float4 qq = qv[half + 2 * (i + 8)];
        d0 += ev1[i].x * qq.x + ev1[i].y * qq.y;
        d1 += ev1[i].z * qq.z + ev1[i].w * qq.w;
        e0 += ev1[i].x * ev1[i].x + ev1[i].y * ev1[i].y;
        e1 += ev1[i].z * ev1[i].z + ev1[i].w * ev1[i].w;
    }
    float dot = d0 + d1;
    float esq = e0 + e1;
    dot += __shfl_xor_sync(0xffffffffu, dot, 1);
    esq += __shfl_xor_sync(0xffffffffu, esq, 1);

    if (half == 0 && c < C)
        g_sims[c] = dot * rqn / fmaxf(sqrtf(esq), 1e-8f);
}

// ---------------------------------------------------------------------------
// Kernel 2: stage-1 top-8. 128 blocks grid-stride over g_sims,
// per-thread sorted list, then smem merge tree.
// ---------------------------------------------------------------------------
__global__ void topk_stage1(int C) {
    __shared__ float sv[256 * KTOP];
    __shared__ int   si[256 * KTOP];
    const int t = threadIdx.x;

    float lv[KTOP]; int li[KTOP];
#pragma unroll
    for (int j = 0; j < KTOP; ++j) { lv[j] = -INFINITY; li[j] = INT_MAX; }

    for (int c = blockIdx.x * blockDim.x + t; c < C; c += gridDim.x * blockDim.x)
        insert_topk(lv, li, g_sims[c], c);

#pragma unroll
    for (int j = 0; j < KTOP; ++j) { sv[t * KTOP + j] = lv[j]; si[t * KTOP + j] = li[j]; }
    __syncthreads();

    for (int s = 128; s > 0; s >>= 1) {
        if (t < s) {
            float mv[KTOP]; int mi[KTOP];
            int a = 0, b = 0;
#pragma unroll
            for (int j = 0; j < KTOP; ++j) {
                const float va = sv[t * KTOP + a];       const int ia = si[t * KTOP + a];
                const float vb = sv[(t + s) * KTOP + b]; const int ib = si[(t + s) * KTOP + b];
                if (better(va, ia, vb, ib)) { mv[j] = va; mi[j] = ia; ++a; }
                else                        { mv[j] = vb; mi[j] = ib; ++b; }
            }
#pragma unroll
            for (int j = 0; j < KTOP; ++j) { sv[t * KTOP + j] = mv[j]; si[t * KTOP + j] = mi[j]; }
        }
        __syncthreads();
    }

    if (t < KTOP) {
        g_cand_v[blockIdx.x * KTOP + t] = sv[t];
        g_cand_i[blockIdx.x * KTOP + t] = si[t];
    }
}

// ---------------------------------------------------------------------------
// Kernel 3: final merge (1024 candidates -> top-8) + gather + scores.
// One block, 1024 threads. Threads 0..255 run the merge; everyone gathers.
// ---------------------------------------------------------------------------
__global__ void __launch_bounds__(1024) final_gather(const float* __restrict__ episodes,
                                                     float* __restrict__ out) {
    __shared__ float sv[256 * KTOP];
    __shared__ int   si[256 * KTOP];
    const int t = threadIdx.x;

    if (t < 256) {
        float lv[KTOP]; int li[KTOP];
#pragma unroll
        for (int j = 0; j < KTOP; ++j) { lv[j] = -INFINITY; li[j] = INT_MAX; }
        for (int c = t; c < NB1 * KTOP; c += 256)
            insert_topk(lv, li, g_cand_v[c], g_cand_i[c]);
#pragma unroll
        for (int j = 0; j < KTOP; ++j) { sv[t * KTOP + j] = lv[j]; si[t * KTOP + j] = li[j]; }
    }
    __syncthreads();

    for (int s = 128; s > 0; s >>= 1) {
        if (t < s) {
            float mv[KTOP]; int mi[KTOP];
            int a = 0, b = 0;
#pragma unroll
            for (int j = 0; j < KTOP; ++j) {
                const float va = sv[t * KTOP + a];       const int ia = si[t * KTOP + a];
                const float vb = sv[(t + s) * KTOP + b]; const int ib = si[(t + s) * KTOP + b];
                if (better(va, ia, vb, ib)) { mv[j] = va; mi[j] = ia; ++a; }
                else                        { mv[j] = vb; mi[j] = ib; ++b; }
            }
#pragma unroll
            for (int j = 0; j < KTOP; ++j) { sv[t * KTOP + j] = mv[j]; si[t * KTOP + j] = mi[j]; }
        }
        __syncthreads();
    }
    // global top-8 in sv[0..7] / si[0..7]

    // ---- gather 8 episodes [8,32,128]: 8192 float4, 8 per thread, independent
    const float4* __restrict__ epi4 = reinterpret_cast<const float4*>(episodes);
    float4* __restrict__ out4 = reinterpret_cast<float4*>(out);
#pragma unroll
    for (int r = 0; r < 8; ++r) {
        const int j   = r * 1024 + t;          // 0..8191
        const int e   = j >> 10;               // episode slot (1024 float4 each)
        const int off = j & 1023;
        const int idx = si[e];
        out4[j] = epi4[(size_t)idx * (SDIM * HDIM / 4) + off];
    }
    if (t < KTOP)
        out[KTOP * SDIM * HDIM + t] = sv[t];   // top_scores[0]
}

extern "C" void kernel_launch(void* const* d_in, const int* in_sizes, int n_in,
                              void* d_out, int out_size) {
    const float* query    = (const float*)d_in[0];  // [B, 128]
    const float* episodes = (const float*)d_in[1];  // [C, 32, 128]
    const float* emb      = (const float*)d_in[2];  // [C, 128]
    (void)n_in; (void)out_size;

    const int C = in_sizes[2] / HDIM;               // 100000

    const int blocksA = (2 * C + 255) / 256;        // 2 lanes per embedding
    sims_kernel<<<blocksA, 256>>>(query, emb, C);
    topk_stage1<<<NB1, 256>>>(C);
    final_gather<<<1, 1024>>>(episodes, (float*)d_out);
}

// round 7
// speedup vs baseline: 1.6174x; 1.0598x over previous
#include <cuda_runtime.h>
#include <math.h>
#include <limits.h>

#define HDIM 128
#define SDIM 32
#define KTOP 8
#define NB1  128      // stage-1 top-k blocks
#define RPW  4        // rows per warp in sims

// Scratch (__device__ globals; no allocation allowed)
__device__ float g_sims[100096];          // padded past C
__device__ float g_cand_v[NB1 * KTOP];
__device__ int   g_cand_i[NB1 * KTOP];
__device__ float g_top_v[KTOP];
__device__ int   g_top_i[KTOP];

__device__ __forceinline__ bool better(float va, int ia, float vb, int ib) {
    // jax.lax.top_k ordering: higher value first, ties -> lower index
    return (va > vb) || (va == vb && ia < ib);
}

__device__ __forceinline__ void insert_topk(float* lv, int* li, float v, int c) {
    if (better(v, c, lv[KTOP - 1], li[KTOP - 1])) {
        int j = KTOP - 1;
#pragma unroll
        for (; j > 0; --j) {
            if (better(v, c, lv[j - 1], li[j - 1])) {
                lv[j] = lv[j - 1];
                li[j] = li[j - 1];
            } else break;
        }
        lv[j] = v;
        li[j] = c;
    }
}

// Shared-memory merge tree: 256 sorted top-8 lists -> slot 0 holds block top-8.
__device__ __forceinline__ void block_merge_topk(float* sv, int* si) {
    const int t = threadIdx.x;
    for (int s = 128; s > 0; s >>= 1) {
        if (t < s) {
            float mv[KTOP]; int mi[KTOP];
            int a = 0, b = 0;
#pragma unroll
            for (int j = 0; j < KTOP; ++j) {
                const float va = sv[t * KTOP + a];       const int ia = si[t * KTOP + a];
                const float vb = sv[(t + s) * KTOP + b]; const int ib = si[(t + s) * KTOP + b];
                if (better(va, ia, vb, ib)) { mv[j] = va; mi[j] = ia; ++a; }
                else                        { mv[j] = vb; mi[j] = ib; ++b; }
            }
#pragma unroll
            for (int j = 0; j < KTOP; ++j) { sv[t * KTOP + j] = mv[j]; si[t * KTOP + j] = mi[j]; }
        }
        __syncthreads();
    }
}

// ---------------------------------------------------------------------------
// Kernel 1: cosine sims, warp-per-embedding, 4 rows per warp.
// Every LDG.128 is a fully coalesced 512B warp access (nL=4, the minimum) —
// fixes the 16-line sector-scattered pattern that capped R3-R6 at 46% DRAM.
// 4 front-batched loads per lane, then interleaved butterfly reductions.
// ---------------------------------------------------------------------------
__global__ void __launch_bounds__(256)
sims_kernel(const float* __restrict__ q,
            const float* __restrict__ emb,
            int C) {
    __shared__ float sq[HDIM];
    __shared__ float s_rqn;
    const int t    = threadIdx.x;
    const int lane = t & 31;

    if (t < HDIM) sq[t] = q[t];               // query row 0
    __syncthreads();
    if (t < 32) {
        const float4 a = reinterpret_cast<const float4*>(sq)[t];
        float s = a.x * a.x + a.y * a.y + a.z * a.z + a.w * a.w;
#pragma unroll
        for (int o = 16; o; o >>= 1) s += __shfl_xor_sync(0xffffffffu, s, o);
        if (t == 0) s_rqn = 1.0f / fmaxf(sqrtf(s), 1e-8f);
    }
    __syncthreads();
    const float rqn = s_rqn;
    const float4 q4 = reinterpret_cast<const float4*>(sq)[lane];

    const int warp = blockIdx.x * (blockDim.x >> 5) + (t >> 5);
    const int r0   = warp * RPW;              // first row of this warp
    const float4* __restrict__ emb4 = reinterpret_cast<const float4*>(emb);

    // Front-batched coalesced loads: 4 independent warp-wide 512B reads.
    float4 ev[RPW];
#pragma unroll
    for (int j = 0; j < RPW; ++j) {
        const int r = min(r0 + j, C - 1);     // clamp; store is guarded
        ev[j] = emb4[(size_t)r * (HDIM / 4) + lane];
    }

    float dot[RPW], esq[RPW];
#pragma unroll
    for (int j = 0; j < RPW; ++j) {
        dot[j] = ev[j].x * q4.x + ev[j].y * q4.y + ev[j].z * q4.z + ev[j].w * q4.w;
        esq[j] = ev[j].x * ev[j].x + ev[j].y * ev[j].y + ev[j].z * ev[j].z + ev[j].w * ev[j].w;
    }
    // Interleaved butterflies: 8 independent shfl chains -> high ILP.
#pragma unroll
    for (int o = 16; o; o >>= 1) {
#pragma unroll
        for (int j = 0; j < RPW; ++j) {
            dot[j] += __shfl_xor_sync(0xffffffffu, dot[j], o);
            esq[j] += __shfl_xor_sync(0xffffffffu, esq[j], o);
        }
    }

    if (lane < RPW) {
        const int r = r0 + lane;
        if (r < C)
            g_sims[r] = dot[lane] * rqn / fmaxf(sqrtf(esq[lane]), 1e-8f);
    }
}

// ---------------------------------------------------------------------------
// Kernel 2: stage-1 top-8. 128 blocks grid-stride over g_sims.
// ---------------------------------------------------------------------------
__global__ void topk_stage1(int C) {
    __shared__ float sv[256 * KTOP];
    __shared__ int   si[256 * KTOP];
    const int t = threadIdx.x;

    float lv[KTOP]; int li[KTOP];
#pragma unroll
    for (int j = 0; j < KTOP; ++j) { lv[j] = -INFINITY; li[j] = INT_MAX; }

    for (int c = blockIdx.x * blockDim.x + t; c < C; c += gridDim.x * blockDim.x)
        insert_topk(lv, li, g_sims[c], c);

#pragma unroll
    for (int j = 0; j < KTOP; ++j) { sv[t * KTOP + j] = lv[j]; si[t * KTOP + j] = li[j]; }
    __syncthreads();
    block_merge_topk(sv, si);

    if (t < KTOP) {
        g_cand_v[blockIdx.x * KTOP + t] = sv[t];
        g_cand_i[blockIdx.x * KTOP + t] = si[t];
    }
}

// ---------------------------------------------------------------------------
// Kernel 3: merge 1024 candidates -> global top-8; write scores into out.
// ---------------------------------------------------------------------------
__global__ void topk_final(float* __restrict__ out) {
    __shared__ float sv[256 * KTOP];
    __shared__ int   si[256 * KTOP];
    const int t = threadIdx.x;

    float lv[KTOP]; int li[KTOP];
#pragma unroll
    for (int j = 0; j < KTOP; ++j) { lv[j] = -INFINITY; li[j] = INT_MAX; }

    for (int c = t; c < NB1 * KTOP; c += 256)
        insert_topk(lv, li, g_cand_v[c], g_cand_i[c]);

#pragma unroll
    for (int j = 0; j < KTOP; ++j) { sv[t * KTOP + j] = lv[j]; si[t * KTOP + j] = li[j]; }
    __syncthreads();
    block_merge_topk(sv, si);

    if (t < KTOP) {
        g_top_v[t] = sv[t];
        g_top_i[t] = si[t];
        out[KTOP * SDIM * HDIM + t] = sv[t];   // top_scores[0]
    }
}

// ---------------------------------------------------------------------------
// Kernel 4: gather top-8 episodes [8,32,128]; 8 blocks per episode.
// ---------------------------------------------------------------------------
__global__ void gather_kernel(const float* __restrict__ episodes,
                              float* __restrict__ out) {
    const int e    = blockIdx.x >> 3;
    const int part = blockIdx.x & 7;
    const int idx  = g_top_i[e];

    const int per = (SDIM * HDIM / 4) / 8;    // 128 float4 per block
    const float4* __restrict__ src =
        reinterpret_cast<const float4*>(episodes + (size_t)idx * (SDIM * HDIM)) + part * per;
    float4* __restrict__ dst =
        reinterpret_cast<float4*>(out + (size_t)e * (SDIM * HDIM)) + part * per;

    if (threadIdx.x < per) dst[threadIdx.x] = src[threadIdx.x];
}

extern "C" void kernel_launch(void* const* d_in, const int* in_sizes, int n_in,
                              void* d_out, int out_size) {
    const float* query    = (const float*)d_in[0];  // [B, 128]
    const float* episodes = (const float*)d_in[1];  // [C, 32, 128]
    const float* emb      = (const float*)d_in[2];  // [C, 128]
    (void)n_in; (void)out_size;

    const int C = in_sizes[2] / HDIM;               // 100000

    // warp handles RPW rows; 8 warps per block
    const int nwarps  = (C + RPW - 1) / RPW;        // 25000
    const int blocksA = (nwarps + 7) / 8;           // 3125
    sims_kernel<<<blocksA, 256>>>(query, emb, C);
    topk_stage1<<<NB1, 256>>>(C);
    topk_final<<<1, 256>>>((float*)d_out);
    gather_kernel<<<64, 128>>>(episodes, (float*)d_out);
}